// round 11
// baseline (speedup 1.0000x reference)
#include <cuda_runtime.h>
#include <cuda_bf16.h>

// Rolling window stats, W=64, F=32 columns. float2, T=48 outputs/thread.
// out[t, 0:32]=mean, [32:64]=std(pop), [64:96]=min, [96:128]=max, [128:160]=sum
//
// R11 = R10 body (best: 34.8us) with TILE 32->48 to amortize the 48-row
// middle-chunk prologue over more outputs (3.5 -> 3.0 loads/output, -8% L1
// wavefronts; L1 at 55.8% is the top SOL). The group loop is ROLLED
// (#pragma unroll 1) so the body stays ~one group (~8-10KB) and fits L1.5 I$
// (R7 lesson: dual 16KB bodies thrashed I$). Grid 1365 CTAs still demands
// 9.2 CTAs/SM > the 8-CTA reg cap, so resident warps are unchanged.
// All R10 details kept: per-emit guards, load clamp, reversed hlo issue,
// tail-w prefetch before H build, __stcs, launch_bounds(64,8).

#define F 32
#define OUT_STRIDE 160
#define TILE 48
#define NGROUPS (TILE / 16)

__device__ __forceinline__ float2 f2add(float2 a, float2 b) {
    float2 r;
    asm("add.rn.f32x2 %0, %1, %2;"
        : "=l"(reinterpret_cast<unsigned long long&>(r))
        : "l"(reinterpret_cast<unsigned long long&>(a)),
          "l"(reinterpret_cast<unsigned long long&>(b)));
    return r;
}
__device__ __forceinline__ float2 f2fma(float2 a, float2 b, float2 c) {
    float2 r;
    asm("fma.rn.f32x2 %0, %1, %2, %3;"
        : "=l"(reinterpret_cast<unsigned long long&>(r))
        : "l"(reinterpret_cast<unsigned long long&>(a)),
          "l"(reinterpret_cast<unsigned long long&>(b)),
          "l"(reinterpret_cast<unsigned long long&>(c)));
    return r;
}
__device__ __forceinline__ float2 f2min(float2 a, float2 b) {
    return make_float2(fminf(a.x, b.x), fminf(a.y, b.y));
}
__device__ __forceinline__ float2 f2max(float2 a, float2 b) {
    return make_float2(fmaxf(a.x, b.x), fmaxf(a.y, b.y));
}
__device__ __forceinline__ float fsqrt_approx(float x) {
    float r;
    asm("sqrt.approx.f32 %0, %1;" : "=f"(r) : "f"(x));
    return r;
}

__global__ __launch_bounds__(64, 8)
void rolling_stats_kernel(const float* __restrict__ x,
                          float* __restrict__ out,
                          int N, int Nout) {
    const int vtid = blockIdx.x * blockDim.x + threadIdx.x;
    const int pair = vtid & 15;          // float2 column pair (0..15)
    const int tile = vtid >> 4;          // 48-output tile index
    const int t0 = tile * TILE;
    if (t0 >= Nout) return;

    const float2* __restrict__ xc = reinterpret_cast<const float2*>(x) + pair;
    const float INF = __int_as_float(0x7f800000);
    const float2 ZERO2 = make_float2(0.f, 0.f);
    const float2 INF2  = make_float2(INF, INF);
    const float2 NINF2 = make_float2(-INF, -INF);
    const float2 INV2  = make_float2(1.0f/64.0f, 1.0f/64.0f);
    const int nclamp = N - 1;

    auto LD = [&](int r) -> float2 {
        r = min(r, nclamp);
        return __ldg(xc + (size_t)r * 16);
    };

    // middle chunk aggregates: rows [t0+16, t0+64)
    float2 a_s[3], a_q[3], a_mn[3], a_mx[3];
#pragma unroll
    for (int c = 0; c < 3; c++) {
        float2 s = ZERO2, q = ZERO2, mn = INF2, mx = NINF2;
        const int base = t0 + 16 + c * 16;
#pragma unroll
        for (int j = 0; j < 16; j++) {
            float2 v = LD(base + j);
            s = f2add(s, v); q = f2fma(v, v, q);
            mn = f2min(mn, v); mx = f2max(mx, v);
        }
        a_s[c] = s; a_q[c] = q; a_mn[c] = mn; a_mx[c] = mx;
    }

#pragma unroll 1
    for (int g = 0; g < NGROUPS; g++) {
        const int hbase = t0 + g * 16;   // head chunk rows [hbase, hbase+16)
        const int tbase = hbase + 64;    // tail chunk rows [tbase, tbase+16)

        const float2 M_s  = f2add(a_s[0], f2add(a_s[1], a_s[2]));
        const float2 M_q  = f2add(a_q[0], f2add(a_q[1], a_q[2]));
        const float2 M_mn = f2min(a_mn[0], f2min(a_mn[1], a_mn[2]));
        const float2 M_mx = f2max(a_mx[0], f2max(a_mx[1], a_mx[2]));

        // load head: hhi forward (M8 fold consumes forward),
        // hlo REVERSED (H build consumes hlo[7] first)
        float2 hlo[8], hhi[8];
#pragma unroll
        for (int j = 0; j < 8; j++) hhi[j] = LD(hbase + 8 + j);
#pragma unroll
        for (int j = 7; j >= 0; j--) hlo[j] = LD(hbase + j);

        // M8 = M ⊕ agg(head[8..15])
        float2 M8_s = M_s, M8_q = M_q, M8_mn = M_mn, M8_mx = M_mx;
#pragma unroll
        for (int j = 0; j < 8; j++) {
            const float2 v = hhi[j];
            M8_s = f2add(M8_s, v); M8_q = f2fma(v, v, M8_q);
            M8_mn = f2min(M8_mn, v); M8_mx = f2max(M8_mx, v);
        }

        float2 t_s = ZERO2, t_q = ZERO2, t_mn = INF2, t_mx = NINF2;
        float2 H_s[8], H_q[8], H_mn[8], H_mx[8];

        // ---- first half: prefetch tail w BEFORE H build (latency overlap) ----
        {
            float2 w[8];
#pragma unroll
            for (int j = 0; j < 8; j++) w[j] = LD(tbase + j);

            // H[r] = M8 ⊕ suffix(hlo[r..7])
            {
                float2 s = M8_s, q = M8_q, mn = M8_mn, mx = M8_mx;
#pragma unroll
                for (int j = 7; j >= 0; j--) {
                    const float2 v = hlo[j];
                    s = f2add(s, v); q = f2fma(v, v, q);
                    mn = f2min(mn, v); mx = f2max(mx, v);
                    H_s[j] = s; H_q[j] = q; H_mn[j] = mn; H_mx[j] = mx;
                }
            }
#pragma unroll
            for (int r = 0; r < 8; r++) {
                const int t = hbase + r;
                const float2 S  = f2add(H_s[r], t_s);
                const float2 Q  = f2add(H_q[r], t_q);
                const float2 mn = f2min(H_mn[r], t_mn);
                const float2 mx = f2max(H_mx[r], t_mx);
                if (t < Nout) {
                    const float2 mean = f2fma(S, INV2, ZERO2);
                    const float2 m2 = f2fma(mean, mean, ZERO2);
                    const float2 var = f2fma(Q, INV2, make_float2(-m2.x, -m2.y));
                    const float2 sd = make_float2(fsqrt_approx(fmaxf(var.x, 0.f)),
                                                  fsqrt_approx(fmaxf(var.y, 0.f)));
                    float2* o = reinterpret_cast<float2*>(out + (size_t)t * OUT_STRIDE) + pair;
                    __stcs(o,      mean);
                    __stcs(o + 16, sd);
                    __stcs(o + 32, mn);
                    __stcs(o + 48, mx);
                    __stcs(o + 64, S);
                }
                const float2 v = w[r];
                t_s = f2add(t_s, v); t_q = f2fma(v, v, t_q);
                t_mn = f2min(t_mn, v); t_mx = f2max(t_mx, v);
            }
        }

        // ---- second half: same pattern ----
        {
            float2 w[8];
#pragma unroll
            for (int j = 0; j < 8; j++) w[j] = LD(tbase + 8 + j);

            // H[r] = M ⊕ suffix(hhi[r..7])
            {
                float2 s = M_s, q = M_q, mn = M_mn, mx = M_mx;
#pragma unroll
                for (int j = 7; j >= 0; j--) {
                    const float2 v = hhi[j];
                    s = f2add(s, v); q = f2fma(v, v, q);
                    mn = f2min(mn, v); mx = f2max(mx, v);
                    H_s[j] = s; H_q[j] = q; H_mn[j] = mn; H_mx[j] = mx;
                }
            }
#pragma unroll
            for (int r = 0; r < 8; r++) {
                const int t = hbase + 8 + r;
                const float2 S  = f2add(H_s[r], t_s);
                const float2 Q  = f2add(H_q[r], t_q);
                const float2 mn = f2min(H_mn[r], t_mn);
                const float2 mx = f2max(H_mx[r], t_mx);
                if (t < Nout) {
                    const float2 mean = f2fma(S, INV2, ZERO2);
                    const float2 m2 = f2fma(mean, mean, ZERO2);
                    const float2 var = f2fma(Q, INV2, make_float2(-m2.x, -m2.y));
                    const float2 sd = make_float2(fsqrt_approx(fmaxf(var.x, 0.f)),
                                                  fsqrt_approx(fmaxf(var.y, 0.f)));
                    float2* o = reinterpret_cast<float2*>(out + (size_t)t * OUT_STRIDE) + pair;
                    __stcs(o,      mean);
                    __stcs(o + 16, sd);
                    __stcs(o + 32, mn);
                    __stcs(o + 48, mx);
                    __stcs(o + 64, S);
                }
                const float2 v = w[r];
                t_s = f2add(t_s, v); t_q = f2fma(v, v, t_q);
                t_mn = f2min(t_mn, v); t_mx = f2max(t_mx, v);
            }
        }

        // roll middle chunk window
        a_s[0] = a_s[1]; a_q[0] = a_q[1]; a_mn[0] = a_mn[1]; a_mx[0] = a_mx[1];
        a_s[1] = a_s[2]; a_q[1] = a_q[2]; a_mn[1] = a_mn[2]; a_mx[1] = a_mx[2];
        a_s[2] = t_s;    a_q[2] = t_q;    a_mn[2] = t_mn;    a_mx[2] = t_mx;
    }
}

extern "C" void kernel_launch(void* const* d_in, const int* in_sizes, int n_in,
                              void* d_out, int out_size) {
    const float* x = (const float*)d_in[0];
    float* out = (float*)d_out;
    const int total = in_sizes[0];
    const int N = total / F;                      // 262144 rows
    const int Nout = N - 63;                      // 262081 output rows
    const int ntiles = (Nout + TILE - 1) / TILE;  // 5460 tiles of 48 outputs
    const int nvthreads = ntiles * 16;            // 16 column-pair threads/tile
    const int block = 64;
    const int grid = (nvthreads + block - 1) / block;
    rolling_stats_kernel<<<grid, block>>>(x, out, N, Nout);
}

// round 13
// speedup vs baseline: 1.1200x; 1.1200x over previous
#include <cuda_runtime.h>
#include <cuda_bf16.h>

// Rolling window stats, W=64, F=32 columns. float2, T=32 outputs/thread.
// out[t, 0:32]=mean, [32:64]=std(pop), [64:96]=min, [96:128]=max, [128:160]=sum
//
// R12 = R10 (best: 34.8us, reproduced) + one pure reorder: the FIRST half's
// tail w[8] prefetch is issued immediately after the head loads, BEFORE the
// M8 fold, so its L2 latency overlaps fold + H build (~64 ops) instead of
// only the H build. Second half unchanged (moving it would exceed the 128-reg
// cap during the first emit loop). Instruction count identical to R10.
// TILE=48/rolled-loop (R11) regressed: full unroll + 2048-CTA grid is the
// confirmed equilibrium. Guards, clamp, __stcs, launch_bounds(64,8) kept.

#define F 32
#define OUT_STRIDE 160
#define TILE 32

__device__ __forceinline__ float2 f2add(float2 a, float2 b) {
    float2 r;
    asm("add.rn.f32x2 %0, %1, %2;"
        : "=l"(reinterpret_cast<unsigned long long&>(r))
        : "l"(reinterpret_cast<unsigned long long&>(a)),
          "l"(reinterpret_cast<unsigned long long&>(b)));
    return r;
}
__device__ __forceinline__ float2 f2fma(float2 a, float2 b, float2 c) {
    float2 r;
    asm("fma.rn.f32x2 %0, %1, %2, %3;"
        : "=l"(reinterpret_cast<unsigned long long&>(r))
        : "l"(reinterpret_cast<unsigned long long&>(a)),
          "l"(reinterpret_cast<unsigned long long&>(b)),
          "l"(reinterpret_cast<unsigned long long&>(c)));
    return r;
}
__device__ __forceinline__ float2 f2min(float2 a, float2 b) {
    return make_float2(fminf(a.x, b.x), fminf(a.y, b.y));
}
__device__ __forceinline__ float2 f2max(float2 a, float2 b) {
    return make_float2(fmaxf(a.x, b.x), fmaxf(a.y, b.y));
}
__device__ __forceinline__ float fsqrt_approx(float x) {
    float r;
    asm("sqrt.approx.f32 %0, %1;" : "=f"(r) : "f"(x));
    return r;
}

__global__ __launch_bounds__(64, 8)
void rolling_stats_kernel(const float* __restrict__ x,
                          float* __restrict__ out,
                          int N, int Nout) {
    const int vtid = blockIdx.x * blockDim.x + threadIdx.x;
    const int pair = vtid & 15;          // float2 column pair (0..15)
    const int tile = vtid >> 4;          // 32-output tile index
    const int t0 = tile * TILE;
    if (t0 >= Nout) return;

    const float2* __restrict__ xc = reinterpret_cast<const float2*>(x) + pair;
    const float INF = __int_as_float(0x7f800000);
    const float2 ZERO2 = make_float2(0.f, 0.f);
    const float2 INF2  = make_float2(INF, INF);
    const float2 NINF2 = make_float2(-INF, -INF);
    const float2 INV2  = make_float2(1.0f/64.0f, 1.0f/64.0f);
    const int nclamp = N - 1;

    auto LD = [&](int r) -> float2 {
        r = min(r, nclamp);
        return __ldg(xc + (size_t)r * 16);
    };

    // middle chunk aggregates: rows [t0+16, t0+64)
    float2 a_s[3], a_q[3], a_mn[3], a_mx[3];
#pragma unroll
    for (int c = 0; c < 3; c++) {
        float2 s = ZERO2, q = ZERO2, mn = INF2, mx = NINF2;
        const int base = t0 + 16 + c * 16;
#pragma unroll
        for (int j = 0; j < 16; j++) {
            float2 v = LD(base + j);
            s = f2add(s, v); q = f2fma(v, v, q);
            mn = f2min(mn, v); mx = f2max(mx, v);
        }
        a_s[c] = s; a_q[c] = q; a_mn[c] = mn; a_mx[c] = mx;
    }

#pragma unroll
    for (int g = 0; g < TILE / 16; g++) {
        const int hbase = t0 + g * 16;   // head chunk rows [hbase, hbase+16)
        const int tbase = hbase + 64;    // tail chunk rows [tbase, tbase+16)

        const float2 M_s  = f2add(a_s[0], f2add(a_s[1], a_s[2]));
        const float2 M_q  = f2add(a_q[0], f2add(a_q[1], a_q[2]));
        const float2 M_mn = f2min(a_mn[0], f2min(a_mn[1], a_mn[2]));
        const float2 M_mx = f2max(a_mx[0], f2max(a_mx[1], a_mx[2]));

        // load head: hhi forward (M8 fold consumes forward),
        // hlo REVERSED (H build consumes hlo[7] first)
        float2 hlo[8], hhi[8];
#pragma unroll
        for (int j = 0; j < 8; j++) hhi[j] = LD(hbase + 8 + j);
#pragma unroll
        for (int j = 7; j >= 0; j--) hlo[j] = LD(hbase + j);

        // FIRST-half tail prefetch issued HERE (before the M8 fold) so its
        // L2 latency overlaps fold + H build instead of only the H build.
        float2 w1[8];
#pragma unroll
        for (int j = 0; j < 8; j++) w1[j] = LD(tbase + j);

        // M8 = M ⊕ agg(head[8..15])
        float2 M8_s = M_s, M8_q = M_q, M8_mn = M_mn, M8_mx = M_mx;
#pragma unroll
        for (int j = 0; j < 8; j++) {
            const float2 v = hhi[j];
            M8_s = f2add(M8_s, v); M8_q = f2fma(v, v, M8_q);
            M8_mn = f2min(M8_mn, v); M8_mx = f2max(M8_mx, v);
        }

        float2 t_s = ZERO2, t_q = ZERO2, t_mn = INF2, t_mx = NINF2;
        float2 H_s[8], H_q[8], H_mn[8], H_mx[8];

        // ---- first half ----
        {
            // H[r] = M8 ⊕ suffix(hlo[r..7])
            {
                float2 s = M8_s, q = M8_q, mn = M8_mn, mx = M8_mx;
#pragma unroll
                for (int j = 7; j >= 0; j--) {
                    const float2 v = hlo[j];
                    s = f2add(s, v); q = f2fma(v, v, q);
                    mn = f2min(mn, v); mx = f2max(mx, v);
                    H_s[j] = s; H_q[j] = q; H_mn[j] = mn; H_mx[j] = mx;
                }
            }
#pragma unroll
            for (int r = 0; r < 8; r++) {
                const int t = hbase + r;
                const float2 S  = f2add(H_s[r], t_s);
                const float2 Q  = f2add(H_q[r], t_q);
                const float2 mn = f2min(H_mn[r], t_mn);
                const float2 mx = f2max(H_mx[r], t_mx);
                if (t < Nout) {
                    const float2 mean = f2fma(S, INV2, ZERO2);
                    const float2 m2 = f2fma(mean, mean, ZERO2);
                    const float2 var = f2fma(Q, INV2, make_float2(-m2.x, -m2.y));
                    const float2 sd = make_float2(fsqrt_approx(fmaxf(var.x, 0.f)),
                                                  fsqrt_approx(fmaxf(var.y, 0.f)));
                    float2* o = reinterpret_cast<float2*>(out + (size_t)t * OUT_STRIDE) + pair;
                    __stcs(o,      mean);
                    __stcs(o + 16, sd);
                    __stcs(o + 32, mn);
                    __stcs(o + 48, mx);
                    __stcs(o + 64, S);
                }
                const float2 v = w1[r];
                t_s = f2add(t_s, v); t_q = f2fma(v, v, t_q);
                t_mn = f2min(t_mn, v); t_mx = f2max(t_mx, v);
            }
        }

        // ---- second half (prefetch placement as in R10) ----
        {
            float2 w[8];
#pragma unroll
            for (int j = 0; j < 8; j++) w[j] = LD(tbase + 8 + j);

            // H[r] = M ⊕ suffix(hhi[r..7])
            {
                float2 s = M_s, q = M_q, mn = M_mn, mx = M_mx;
#pragma unroll
                for (int j = 7; j >= 0; j--) {
                    const float2 v = hhi[j];
                    s = f2add(s, v); q = f2fma(v, v, q);
                    mn = f2min(mn, v); mx = f2max(mx, v);
                    H_s[j] = s; H_q[j] = q; H_mn[j] = mn; H_mx[j] = mx;
                }
            }
#pragma unroll
            for (int r = 0; r < 8; r++) {
                const int t = hbase + 8 + r;
                const float2 S  = f2add(H_s[r], t_s);
                const float2 Q  = f2add(H_q[r], t_q);
                const float2 mn = f2min(H_mn[r], t_mn);
                const float2 mx = f2max(H_mx[r], t_mx);
                if (t < Nout) {
                    const float2 mean = f2fma(S, INV2, ZERO2);
                    const float2 m2 = f2fma(mean, mean, ZERO2);
                    const float2 var = f2fma(Q, INV2, make_float2(-m2.x, -m2.y));
                    const float2 sd = make_float2(fsqrt_approx(fmaxf(var.x, 0.f)),
                                                  fsqrt_approx(fmaxf(var.y, 0.f)));
                    float2* o = reinterpret_cast<float2*>(out + (size_t)t * OUT_STRIDE) + pair;
                    __stcs(o,      mean);
                    __stcs(o + 16, sd);
                    __stcs(o + 32, mn);
                    __stcs(o + 48, mx);
                    __stcs(o + 64, S);
                }
                const float2 v = w[r];
                t_s = f2add(t_s, v); t_q = f2fma(v, v, t_q);
                t_mn = f2min(t_mn, v); t_mx = f2max(t_mx, v);
            }
        }

        // roll middle chunk window
        a_s[0] = a_s[1]; a_q[0] = a_q[1]; a_mn[0] = a_mn[1]; a_mx[0] = a_mx[1];
        a_s[1] = a_s[2]; a_q[1] = a_q[2]; a_mn[1] = a_mn[2]; a_mx[1] = a_mx[2];
        a_s[2] = t_s;    a_q[2] = t_q;    a_mn[2] = t_mn;    a_mx[2] = t_mx;
    }
}

extern "C" void kernel_launch(void* const* d_in, const int* in_sizes, int n_in,
                              void* d_out, int out_size) {
    const float* x = (const float*)d_in[0];
    float* out = (float*)d_out;
    const int total = in_sizes[0];
    const int N = total / F;                 // 262144 rows
    const int Nout = N - 63;                 // 262081 output rows
    const int ntiles = (Nout + TILE - 1) / TILE;  // 8191 tiles of 32 outputs
    const int nvthreads = ntiles * 16;       // 16 column-pair threads per tile
    const int block = 64;
    const int grid = (nvthreads + block - 1) / block;
    rolling_stats_kernel<<<grid, block>>>(x, out, N, Nout);
}